// round 1
// baseline (speedup 1.0000x reference)
#include <cuda_runtime.h>
#include <math.h>

// Problem constants
#define PB 4
#define PL 1024
#define PE 1024
#define PH 16
#define PD 64
#define PHID 1024
#define PR 4
#define PM 4096   // B*L

// -------- scratch (device globals; no allocation in kernel_launch) --------
__device__ float g_qkvg[(size_t)PM * 4096];          // 64 MB: q|k|tanh(v)|sigmoid(g)
__device__ float g_gated[(size_t)PM * PHID];         // 16 MB
__device__ float g_w_fb[(size_t)PB * PL * PL * PH];  // 256 MB fallback for w
__device__ float g_out_fb[(size_t)PM * PE];          // 16 MB fallback for out
__device__ int   g_kpm_mode;                         // 0=u8, 1=f32, 2=i32

// -------- key_padding_mask dtype detector --------
__global__ void detect_kpm_kernel(const unsigned char* __restrict__ p) {
    bool any_gt1 = false, any_off_nonzero = false;
    for (int i = 0; i < 256; i++) {
        unsigned char v = p[i];
        if (v > 1) any_gt1 = true;
        if ((i & 3) != 0 && v != 0) any_off_nonzero = true;
    }
    int mode;
    if (any_gt1) mode = 1;            // float32 (bytes like 0x80/0x3F present)
    else if (!any_off_nonzero) mode = 2; // int32 (non-LSB bytes all zero)
    else mode = 0;                    // uint8/bool
    g_kpm_mode = mode;
}

// -------- SGEMM (NT): C[M,N] = A[M,K] * B[N,K]^T + bias[n], optional qkvg epilogue --------
// BM=BN=128, BK=16, 256 threads, 8x8 micro (two 4-wide subtiles per dim)
__global__ __launch_bounds__(256, 2) void sgemm_nt(
    int M, int N, int K,
    const float* __restrict__ A,
    const float* __restrict__ B,
    const float* __restrict__ bias,
    float* __restrict__ C,
    int mode)  // 0: bias only; 1: qkvg activations by 1024-col segment
{
    __shared__ float As[16][128];
    __shared__ float Bs[16][128];
    const int bm = blockIdx.y, bn = blockIdx.x;
    const int tid = threadIdx.x;
    const int tx = tid & 15, ty = tid >> 4;
    const int lr = tid >> 2;            // 0..63
    const int lc = (tid & 3) << 2;      // 0,4,8,12

    const float* Ab = A + (size_t)bm * 128 * K;
    const float* Bb = B + (size_t)bn * 128 * K;

    float acc[8][8];
#pragma unroll
    for (int i = 0; i < 8; i++)
#pragma unroll
        for (int j = 0; j < 8; j++) acc[i][j] = 0.f;

    for (int k0 = 0; k0 < K; k0 += 16) {
#pragma unroll
        for (int r = 0; r < 128; r += 64) {
            float4 v = *(const float4*)(Ab + (size_t)(lr + r) * K + k0 + lc);
            As[lc + 0][lr + r] = v.x; As[lc + 1][lr + r] = v.y;
            As[lc + 2][lr + r] = v.z; As[lc + 3][lr + r] = v.w;
            float4 u = *(const float4*)(Bb + (size_t)(lr + r) * K + k0 + lc);
            Bs[lc + 0][lr + r] = u.x; Bs[lc + 1][lr + r] = u.y;
            Bs[lc + 2][lr + r] = u.z; Bs[lc + 3][lr + r] = u.w;
        }
        __syncthreads();
#pragma unroll
        for (int k = 0; k < 16; k++) {
            float ar[8], br[8];
            *(float4*)&ar[0] = *(const float4*)&As[k][ty * 4];
            *(float4*)&ar[4] = *(const float4*)&As[k][64 + ty * 4];
            *(float4*)&br[0] = *(const float4*)&Bs[k][tx * 4];
            *(float4*)&br[4] = *(const float4*)&Bs[k][64 + tx * 4];
#pragma unroll
            for (int i = 0; i < 8; i++)
#pragma unroll
                for (int j = 0; j < 8; j++) acc[i][j] += ar[i] * br[j];
        }
        __syncthreads();
    }

    // Block lies entirely within one 1024-col segment (1024 % 128 == 0)
    const int seg = (mode == 1) ? ((bn * 128) >> 10) : 0;
#pragma unroll
    for (int i = 0; i < 8; i++) {
        const int gm = bm * 128 + ((i < 4) ? (ty * 4 + i) : (64 + ty * 4 + i - 4));
#pragma unroll
        for (int jh = 0; jh < 2; jh++) {
            const int gn = bn * 128 + jh * 64 + tx * 4;
            float vv[4];
#pragma unroll
            for (int c = 0; c < 4; c++) {
                float v = acc[i][jh * 4 + c] + bias[gn + c];
                if (seg == 2) v = tanhf(v);
                else if (seg == 3) v = 1.f / (1.f + __expf(-v));
                vv[c] = v;
            }
            float4 o; o.x = vv[0]; o.y = vv[1]; o.z = vv[2]; o.w = vv[3];
            *(float4*)(C + (size_t)gm * N + gn) = o;
        }
    }
}

// -------- K2: scores + rels bias + heads-softmax + masks -> w --------
// tile 32x32 (i,j), 256 threads, each thread: 2x2 (i,j) micro x all 16 heads in regs
__global__ __launch_bounds__(256, 2) void scores_kernel(
    const float* __restrict__ qkvg,
    const float* __restrict__ rels,       // [B,L,L,R]
    const float* __restrict__ attn_mask,  // [B,L,L]
    const void*  __restrict__ kpm,        // [B,L,L] dtype per g_kpm_mode
    const float* __restrict__ rels_bias,  // [R,H]
    float* __restrict__ w)                // [B,L,L,H]
{
    __shared__ float sq[32][68];   // pad 68 (272B rows, 16B aligned, conflict-free reads)
    __shared__ float sk[32][68];
    __shared__ float sbias[4][16];

    const int b = blockIdx.z;
    const int i0 = blockIdx.y * 32;
    const int j0 = blockIdx.x * 32;
    const int tid = threadIdx.x;
    if (tid < 64) sbias[tid >> 4][tid & 15] = rels_bias[tid];
    const int tx = tid & 15, ty = tid >> 4;

    float s[4][16];
#pragma unroll
    for (int c = 0; c < 4; c++)
#pragma unroll
        for (int h = 0; h < 16; h++) s[c][h] = 0.f;

#pragma unroll
    for (int h = 0; h < 16; h++) {
        __syncthreads();
#pragma unroll
        for (int t = 0; t < 2; t++) {
            const int f = tid + t * 256;
            const int r = f >> 4;
            const int d = (f & 15) << 2;
            float4 qv = *(const float4*)(qkvg + (size_t)(b * 1024 + i0 + r) * 4096 + h * 64 + d);
            sq[r][d] = qv.x; sq[r][d + 1] = qv.y; sq[r][d + 2] = qv.z; sq[r][d + 3] = qv.w;
            float4 kv = *(const float4*)(qkvg + (size_t)(b * 1024 + j0 + r) * 4096 + 1024 + h * 64 + d);
            sk[r][d] = kv.x; sk[r][d + 1] = kv.y; sk[r][d + 2] = kv.z; sk[r][d + 3] = kv.w;
        }
        __syncthreads();
#pragma unroll
        for (int d4 = 0; d4 < 16; d4++) {
            float4 q0 = *(const float4*)&sq[ty][d4 * 4];
            float4 q1 = *(const float4*)&sq[ty + 16][d4 * 4];
            float4 k0 = *(const float4*)&sk[tx][d4 * 4];
            float4 k1 = *(const float4*)&sk[tx + 16][d4 * 4];
            s[0][h] += q0.x * k0.x + q0.y * k0.y + q0.z * k0.z + q0.w * k0.w;
            s[1][h] += q0.x * k1.x + q0.y * k1.y + q0.z * k1.z + q0.w * k1.w;
            s[2][h] += q1.x * k0.x + q1.y * k0.y + q1.z * k0.z + q1.w * k0.w;
            s[3][h] += q1.x * k1.x + q1.y * k1.y + q1.z * k1.z + q1.w * k1.w;
        }
    }

    const int mode = g_kpm_mode;
#pragma unroll
    for (int ii = 0; ii < 2; ii++) {
#pragma unroll
        for (int jj = 0; jj < 2; jj++) {
            const int c = ii * 2 + jj;
            const int i = i0 + ty + ii * 16;
            const int j = j0 + tx + jj * 16;
            const size_t base = ((size_t)(b * 1024 + i)) * 1024 + j;
            float4 r4 = *(const float4*)(rels + base * 4);
            float sv[16];
            float mx = -1e30f;
#pragma unroll
            for (int h = 0; h < 16; h++) {
                float v = (s[c][h]
                           + r4.x * sbias[0][h] + r4.y * sbias[1][h]
                           + r4.z * sbias[2][h] + r4.w * sbias[3][h]) * 0.125f;
                sv[h] = v;
                mx = fmaxf(mx, v);
            }
            float sum = 0.f;
#pragma unroll
            for (int h = 0; h < 16; h++) { sv[h] = __expf(sv[h] - mx); sum += sv[h]; }
            const float am = attn_mask[base];
            bool pad;
            if (mode == 0)      pad = ((const unsigned char*)kpm)[base] != 0;
            else if (mode == 1) pad = ((const float*)kpm)[base] != 0.0f;
            else                pad = ((const int*)kpm)[base] != 0;
            const float scale = pad ? (__expf(am) / sum) : 0.f;
            float* wp = w + base * 16;
#pragma unroll
            for (int h4 = 0; h4 < 4; h4++) {
                float4 o;
                o.x = sv[h4 * 4 + 0] * scale; o.y = sv[h4 * 4 + 1] * scale;
                o.z = sv[h4 * 4 + 2] * scale; o.w = sv[h4 * 4 + 3] * scale;
                *(float4*)(wp + h4 * 4) = o;
            }
        }
    }
}

// -------- K3: attn_out[b,i,h,d] = sum_j w[b,i,j,h] * tanh_v[b,j,h,d]; * sigmoid_g; -> gated --------
// block: (b, i-tile of 16). 256 threads: thread = (h = tid>>4, dgroup = tid&15 -> 4 d's)
__global__ __launch_bounds__(256) void attn_av_kernel(
    const float* __restrict__ qkvg,
    const float* __restrict__ w,      // [B,L,L,H]
    float* __restrict__ gated)        // [4096, 1024]
{
    __shared__ float stv[8][1024];       // tanh(v) rows for 8 j's
    __shared__ float sw[8][17][16];      // w transposed [j][h][i], padded middle dim

    const int b = blockIdx.y;
    const int i0 = blockIdx.x * 16;
    const int tid = threadIdx.x;
    const int h = tid >> 4;
    const int dg = tid & 15;

    float acc[16][4];
#pragma unroll
    for (int i = 0; i < 16; i++)
#pragma unroll
        for (int c = 0; c < 4; c++) acc[i][c] = 0.f;

    for (int j0 = 0; j0 < 1024; j0 += 8) {
        __syncthreads();
        // tanh(v) tile: 8 rows x 1024 floats
#pragma unroll
        for (int t = 0; t < 8; t++) {
            const int f = tid + t * 256;      // float4 index, 0..2047
            const int j = f >> 8;
            const int c = (f & 255) << 2;
            float4 v = *(const float4*)(qkvg + (size_t)(b * 1024 + j0 + j) * 4096 + 2048 + c);
            *(float4*)&stv[j][c] = v;
        }
        // w tile: [i 16][j 8][h 16] -> smem transposed [j][h][i]
#pragma unroll
        for (int t = 0; t < 2; t++) {
            const int f = tid + t * 256;      // float4 index, 0..511
            const int h4 = (f & 3) << 2;
            const int j = (f >> 2) & 7;
            const int i = f >> 5;
            float4 v = *(const float4*)(w + (((size_t)(b * 1024 + i0 + i)) * 1024 + j0 + j) * 16 + h4);
            sw[j][h4 + 0][i] = v.x; sw[j][h4 + 1][i] = v.y;
            sw[j][h4 + 2][i] = v.z; sw[j][h4 + 3][i] = v.w;
        }
        __syncthreads();
#pragma unroll
        for (int j = 0; j < 8; j++) {
            float4 tv = *(const float4*)&stv[j][h * 64 + dg * 4];
            float wv[16];
#pragma unroll
            for (int q4 = 0; q4 < 4; q4++) {
                float4 wf = *(const float4*)&sw[j][h][q4 * 4];
                wv[q4 * 4 + 0] = wf.x; wv[q4 * 4 + 1] = wf.y;
                wv[q4 * 4 + 2] = wf.z; wv[q4 * 4 + 3] = wf.w;
            }
#pragma unroll
            for (int i = 0; i < 16; i++) {
                acc[i][0] += wv[i] * tv.x;
                acc[i][1] += wv[i] * tv.y;
                acc[i][2] += wv[i] * tv.z;
                acc[i][3] += wv[i] * tv.w;
            }
        }
    }

#pragma unroll
    for (int i = 0; i < 16; i++) {
        const size_t row = (size_t)(b * 1024 + i0 + i);
        float4 sg = *(const float4*)(qkvg + row * 4096 + 3072 + h * 64 + dg * 4);
        float4 o;
        o.x = acc[i][0] * sg.x; o.y = acc[i][1] * sg.y;
        o.z = acc[i][2] * sg.z; o.w = acc[i][3] * sg.w;
        *(float4*)(gated + row * 1024 + h * 64 + dg * 4) = o;
    }
}

// -------- launcher --------
extern "C" void kernel_launch(void* const* d_in, const int* in_sizes, int n_in,
                              void* d_out, int out_size) {
    const float* query     = (const float*)d_in[0];
    const float* rels      = (const float*)d_in[1];
    const float* attn_mask = (const float*)d_in[2];
    const void*  kpm       = d_in[3];
    const float* proj_w    = (const float*)d_in[4];
    const float* proj_b    = (const float*)d_in[5];
    const float* out_w     = (const float*)d_in[6];
    const float* out_b     = (const float*)d_in[7];
    const float* rels_bias = (const float*)d_in[8];

    float *qkvg_p, *gated_p, *wfb_p, *ofb_p;
    cudaGetSymbolAddress((void**)&qkvg_p,  g_qkvg);
    cudaGetSymbolAddress((void**)&gated_p, g_gated);
    cudaGetSymbolAddress((void**)&wfb_p,   g_w_fb);
    cudaGetSymbolAddress((void**)&ofb_p,   g_out_fb);

    const size_t OUT_E = (size_t)PM * PE;                 // 4,194,304
    const size_t W_E   = (size_t)PB * PL * PL * PH;       // 67,108,864
    float* out_p;
    float* w_p;
    const size_t osz = (size_t)out_size;
    if (osz >= OUT_E + W_E)      { out_p = (float*)d_out; w_p = (float*)d_out + OUT_E; }
    else if (osz == W_E)         { w_p = (float*)d_out;  out_p = ofb_p; }
    else                         { out_p = (float*)d_out; w_p = wfb_p; }

    detect_kpm_kernel<<<1, 1>>>((const unsigned char*)kpm);

    // K1: qkvg = query @ proj_w^T + proj_b  (with tanh/sigmoid epilogue on v/g segments)
    sgemm_nt<<<dim3(32, 32), 256>>>(PM, 4096, PE, query, proj_w, proj_b, qkvg_p, 1);

    // K2: scores -> heads-softmax -> masks -> w
    scores_kernel<<<dim3(32, 32, PB), 256>>>(qkvg_p, rels, attn_mask, kpm, rels_bias, w_p);

    // K3: AV + gate
    attn_av_kernel<<<dim3(64, PB), 256>>>(qkvg_p, w_p, gated_p);

    // K4: out = gated @ out_w^T + out_b
    sgemm_nt<<<dim3(8, 32), 256>>>(PM, PE, PHID, gated_p, out_w, out_b, out_p, 0);
}

// round 2
// speedup vs baseline: 1.0773x; 1.0773x over previous
#include <cuda_runtime.h>
#include <math.h>

#define PB 4
#define PL 1024
#define PE 1024
#define PH 16
#define PD 64
#define PHID 1024
#define PR 4
#define PM 4096   // B*L

typedef unsigned long long ULL;

// ---- f32x2 packed helpers ----
__device__ __forceinline__ ULL pk2(float x, float y) {
    ULL r; asm("mov.b64 %0, {%1,%2};" : "=l"(r) : "f"(x), "f"(y)); return r;
}
__device__ __forceinline__ float2 up2(ULL a) {
    float2 r; asm("mov.b64 {%0,%1}, %2;" : "=f"(r.x), "=f"(r.y) : "l"(a)); return r;
}
__device__ __forceinline__ void fma2(ULL& d, ULL a, ULL b) {
    asm("fma.rn.f32x2 %0, %1, %2, %0;" : "+l"(d) : "l"(a), "l"(b));
}

// -------- scratch --------
__device__ float g_qkvg[(size_t)PM * 4096];          // q|k|tanh(v)|sigmoid(g)
__device__ float g_gated[(size_t)PM * PHID];
__device__ float g_w_fb[(size_t)PB * PL * PL * PH];
__device__ float g_out_fb[(size_t)PM * PE];
__device__ int   g_kpm_mode;

__global__ void detect_kpm_kernel(const unsigned char* __restrict__ p) {
    bool any_gt1 = false, any_off_nonzero = false;
    for (int i = 0; i < 256; i++) {
        unsigned char v = p[i];
        if (v > 1) any_gt1 = true;
        if ((i & 3) != 0 && v != 0) any_off_nonzero = true;
    }
    int mode;
    if (any_gt1) mode = 1;
    else if (!any_off_nonzero) mode = 2;
    else mode = 0;
    g_kpm_mode = mode;
}

// -------- SGEMM (NT) with f32x2: C[M,N] = A[M,K]*B[N,K]^T + bias --------
// BM=BN=128, BK=16, 256 threads, micro 8x8 via packed j-pairs
__global__ __launch_bounds__(256, 2) void sgemm_nt(
    int M, int N, int K,
    const float* __restrict__ A,
    const float* __restrict__ B,
    const float* __restrict__ bias,
    float* __restrict__ C,
    int mode)
{
    __shared__ float As[16][132];
    __shared__ float Bs[16][132];
    const int bm = blockIdx.y, bn = blockIdx.x;
    const int tid = threadIdx.x;
    const int tx = tid & 15, ty = tid >> 4;
    const int lr = tid >> 2;
    const int lc = (tid & 3) << 2;

    const float* Ab = A + (size_t)bm * 128 * K;
    const float* Bb = B + (size_t)bn * 128 * K;

    ULL acc[8][4];
#pragma unroll
    for (int i = 0; i < 8; i++)
#pragma unroll
        for (int j = 0; j < 4; j++) acc[i][j] = 0ull;

    for (int k0 = 0; k0 < K; k0 += 16) {
#pragma unroll
        for (int r = 0; r < 128; r += 64) {
            float4 v = *(const float4*)(Ab + (size_t)(lr + r) * K + k0 + lc);
            As[lc + 0][lr + r] = v.x; As[lc + 1][lr + r] = v.y;
            As[lc + 2][lr + r] = v.z; As[lc + 3][lr + r] = v.w;
            float4 u = *(const float4*)(Bb + (size_t)(lr + r) * K + k0 + lc);
            Bs[lc + 0][lr + r] = u.x; Bs[lc + 1][lr + r] = u.y;
            Bs[lc + 2][lr + r] = u.z; Bs[lc + 3][lr + r] = u.w;
        }
        __syncthreads();
#pragma unroll
        for (int k = 0; k < 16; k++) {
            float ar[8];
            *(float4*)&ar[0] = *(const float4*)&As[k][ty * 4];
            *(float4*)&ar[4] = *(const float4*)&As[k][64 + ty * 4];
            ulonglong2 b0 = *(const ulonglong2*)&Bs[k][tx * 4];
            ulonglong2 b1 = *(const ulonglong2*)&Bs[k][64 + tx * 4];
            ULL br0 = b0.x, br1 = b0.y, br2 = b1.x, br3 = b1.y;
#pragma unroll
            for (int i = 0; i < 8; i++) {
                ULL a2 = pk2(ar[i], ar[i]);
                fma2(acc[i][0], a2, br0);
                fma2(acc[i][1], a2, br1);
                fma2(acc[i][2], a2, br2);
                fma2(acc[i][3], a2, br3);
            }
        }
        __syncthreads();
    }

    const int seg = (mode == 1) ? ((bn * 128) >> 10) : 0;
#pragma unroll
    for (int i = 0; i < 8; i++) {
        const int gm = bm * 128 + ((i < 4) ? (ty * 4 + i) : (64 + ty * 4 + i - 4));
#pragma unroll
        for (int g = 0; g < 2; g++) {
            const int gn = bn * 128 + g * 64 + tx * 4;
            float2 p0 = up2(acc[i][g * 2]);
            float2 p1 = up2(acc[i][g * 2 + 1]);
            float vv[4] = {p0.x, p0.y, p1.x, p1.y};
#pragma unroll
            for (int c = 0; c < 4; c++) {
                float v = vv[c] + bias[gn + c];
                if (seg == 2) v = tanhf(v);
                else if (seg == 3) v = 1.f / (1.f + __expf(-v));
                vv[c] = v;
            }
            float4 o; o.x = vv[0]; o.y = vv[1]; o.z = vv[2]; o.w = vv[3];
            *(float4*)(C + (size_t)gm * N + gn) = o;
        }
    }
}

// -------- K2: scores + rels bias + heads-softmax + masks -> w (head-pair packed) --------
__global__ __launch_bounds__(256, 2) void scores_kernel(
    const float* __restrict__ qkvg,
    const float* __restrict__ rels,
    const float* __restrict__ attn_mask,
    const void*  __restrict__ kpm,
    const float* __restrict__ rels_bias,
    float* __restrict__ w)
{
    __shared__ float sq[32][132];   // interleaved: sq[r][2*d+p] = q_{h0+p}[d]
    __shared__ float sk[32][132];
    __shared__ float sbias[4][16];

    const int b = blockIdx.z;
    const int i0 = blockIdx.y * 32;
    const int j0 = blockIdx.x * 32;
    const int tid = threadIdx.x;
    if (tid < 64) sbias[tid >> 4][tid & 15] = rels_bias[tid];
    const int tx = tid & 15, ty = tid >> 4;

    ULL s2[4][8];
#pragma unroll
    for (int c = 0; c < 4; c++)
#pragma unroll
        for (int hp = 0; hp < 8; hp++) s2[c][hp] = 0ull;

#pragma unroll
    for (int hp = 0; hp < 8; hp++) {
        __syncthreads();
#pragma unroll
        for (int t = 0; t < 4; t++) {
            const int f = tid + t * 256;      // 0..1023
            const int r = f >> 5;
            const int u = f & 31;
            const int p = u & 1;
            const int d0 = (u >> 1) << 2;
            float4 qv = *(const float4*)(qkvg + (size_t)(b * 1024 + i0 + r) * 4096 + (2 * hp + p) * 64 + d0);
            sq[r][2 * (d0 + 0) + p] = qv.x; sq[r][2 * (d0 + 1) + p] = qv.y;
            sq[r][2 * (d0 + 2) + p] = qv.z; sq[r][2 * (d0 + 3) + p] = qv.w;
            float4 kv = *(const float4*)(qkvg + (size_t)(b * 1024 + j0 + r) * 4096 + 1024 + (2 * hp + p) * 64 + d0);
            sk[r][2 * (d0 + 0) + p] = kv.x; sk[r][2 * (d0 + 1) + p] = kv.y;
            sk[r][2 * (d0 + 2) + p] = kv.z; sk[r][2 * (d0 + 3) + p] = kv.w;
        }
        __syncthreads();
#pragma unroll 8
        for (int dp = 0; dp < 32; dp++) {
            ulonglong2 Q0 = *(const ulonglong2*)&sq[ty][dp * 4];
            ulonglong2 Q1 = *(const ulonglong2*)&sq[ty + 16][dp * 4];
            ulonglong2 K0 = *(const ulonglong2*)&sk[tx][dp * 4];
            ulonglong2 K1 = *(const ulonglong2*)&sk[tx + 16][dp * 4];
            fma2(s2[0][hp], Q0.x, K0.x); fma2(s2[0][hp], Q0.y, K0.y);
            fma2(s2[1][hp], Q0.x, K1.x); fma2(s2[1][hp], Q0.y, K1.y);
            fma2(s2[2][hp], Q1.x, K0.x); fma2(s2[2][hp], Q1.y, K0.y);
            fma2(s2[3][hp], Q1.x, K1.x); fma2(s2[3][hp], Q1.y, K1.y);
        }
    }

    const int mode = g_kpm_mode;
#pragma unroll
    for (int ii = 0; ii < 2; ii++) {
#pragma unroll
        for (int jj = 0; jj < 2; jj++) {
            const int c = ii * 2 + jj;
            const int i = i0 + ty + ii * 16;
            const int j = j0 + tx + jj * 16;
            const size_t base = ((size_t)(b * 1024 + i)) * 1024 + j;
            float4 r4 = *(const float4*)(rels + base * 4);
            float sv[16];
#pragma unroll
            for (int hp = 0; hp < 8; hp++) {
                float2 v = up2(s2[c][hp]);
                sv[2 * hp] = v.x; sv[2 * hp + 1] = v.y;
            }
            float mx = -1e30f;
#pragma unroll
            for (int h = 0; h < 16; h++) {
                float v = (sv[h]
                           + r4.x * sbias[0][h] + r4.y * sbias[1][h]
                           + r4.z * sbias[2][h] + r4.w * sbias[3][h]) * 0.125f;
                sv[h] = v;
                mx = fmaxf(mx, v);
            }
            float sum = 0.f;
#pragma unroll
            for (int h = 0; h < 16; h++) { sv[h] = __expf(sv[h] - mx); sum += sv[h]; }
            const float am = attn_mask[base];
            bool pad;
            if (mode == 0)      pad = ((const unsigned char*)kpm)[base] != 0;
            else if (mode == 1) pad = ((const float*)kpm)[base] != 0.0f;
            else                pad = ((const int*)kpm)[base] != 0;
            const float scale = pad ? (__expf(am) / sum) : 0.f;
            float* wp = w + base * 16;
#pragma unroll
            for (int h4 = 0; h4 < 4; h4++) {
                float4 o;
                o.x = sv[h4 * 4 + 0] * scale; o.y = sv[h4 * 4 + 1] * scale;
                o.z = sv[h4 * 4 + 2] * scale; o.w = sv[h4 * 4 + 3] * scale;
                *(float4*)(wp + h4 * 4) = o;
            }
        }
    }
}

// -------- K3: attn_out = sum_j w * tanh_v; * sigmoid_g -> gated --------
// 512 threads, i-tile 32, j-step 8, two-pass transpose, f32x2 over i-pairs
__global__ __launch_bounds__(512, 1) void attn_av_kernel(
    const float* __restrict__ qkvg,
    const float* __restrict__ w,
    float* __restrict__ gated)
{
    extern __shared__ float dsm[];
    float* stv = dsm;                     // [8][1024]
    float* raw = dsm + 8 * 1024;          // [32][132]  (w tile, raw: [i][j*16+h])
    float* sw  = raw + 32 * 132;          // [8][17][32] (transposed: [j][h][i])

    const int b = blockIdx.y;
    const int i0 = blockIdx.x * 32;
    const int tid = threadIdx.x;
    const int h = (tid >> 4) & 15;
    const int dg = tid & 15;
    const int ih = tid >> 8;              // 0..1

    ULL acc[8][4];
#pragma unroll
    for (int ip = 0; ip < 8; ip++)
#pragma unroll
        for (int c = 0; c < 4; c++) acc[ip][c] = 0ull;

    for (int j0 = 0; j0 < 1024; j0 += 8) {
        // pass A: load tanh(v) rows and raw w tile
#pragma unroll
        for (int t = 0; t < 4; t++) {
            const int f = tid + t * 512;      // 0..2047 float4
            const int j = f >> 8;
            const int c = (f & 255) << 2;
            float4 v = *(const float4*)(qkvg + (size_t)(b * 1024 + j0 + j) * 4096 + 2048 + c);
            *(float4*)&stv[j * 1024 + c] = v;
        }
#pragma unroll
        for (int t = 0; t < 2; t++) {
            const int f = tid + t * 512;      // 0..1023 float4
            const int h4 = (f & 3) << 2;
            const int j = (f >> 2) & 7;
            const int i = f >> 5;
            float4 v = *(const float4*)(w + (((size_t)(b * 1024 + i0 + i)) * 1024 + j0 + j) * 16 + h4);
            *(float4*)&raw[i * 132 + j * 16 + h4] = v;
        }
        __syncthreads();
        // pass B: transpose raw -> sw[j][h][i] (conflict-free stores, bank = i)
#pragma unroll
        for (int t = 0; t < 2; t++) {
            const int g = tid + t * 512;      // 0..1023 float4
            const int i = g & 31;
            const int q = g >> 5;             // 0..31 -> col q*4
            float4 v = *(const float4*)&raw[i * 132 + q * 4];
            const int j = q >> 2;
            const int h4 = (q & 3) << 2;
            sw[(j * 17 + h4 + 0) * 32 + i] = v.x;
            sw[(j * 17 + h4 + 1) * 32 + i] = v.y;
            sw[(j * 17 + h4 + 2) * 32 + i] = v.z;
            sw[(j * 17 + h4 + 3) * 32 + i] = v.w;
        }
        __syncthreads();
#pragma unroll
        for (int j = 0; j < 8; j++) {
            float4 tv = *(const float4*)&stv[j * 1024 + h * 64 + dg * 4];
            ULL t0 = pk2(tv.x, tv.x), t1 = pk2(tv.y, tv.y);
            ULL t2 = pk2(tv.z, tv.z), t3 = pk2(tv.w, tv.w);
            const float* wb = &sw[(j * 17 + h) * 32 + ih * 16];
            ulonglong2 wA = *(const ulonglong2*)&wb[0];
            ulonglong2 wB = *(const ulonglong2*)&wb[4];
            ulonglong2 wC = *(const ulonglong2*)&wb[8];
            ulonglong2 wD = *(const ulonglong2*)&wb[12];
            ULL wp[8] = {wA.x, wA.y, wB.x, wB.y, wC.x, wC.y, wD.x, wD.y};
#pragma unroll
            for (int ip = 0; ip < 8; ip++) {
                fma2(acc[ip][0], wp[ip], t0);
                fma2(acc[ip][1], wp[ip], t1);
                fma2(acc[ip][2], wp[ip], t2);
                fma2(acc[ip][3], wp[ip], t3);
            }
        }
        __syncthreads();
    }

#pragma unroll
    for (int ip = 0; ip < 8; ip++) {
        const size_t row0 = (size_t)(b * 1024 + i0 + ih * 16 + 2 * ip);
        float2 c0 = up2(acc[ip][0]), c1 = up2(acc[ip][1]);
        float2 c2 = up2(acc[ip][2]), c3 = up2(acc[ip][3]);
        float4 sg0 = *(const float4*)(qkvg + row0 * 4096 + 3072 + h * 64 + dg * 4);
        float4 sg1 = *(const float4*)(qkvg + (row0 + 1) * 4096 + 3072 + h * 64 + dg * 4);
        float4 o0; o0.x = c0.x * sg0.x; o0.y = c1.x * sg0.y; o0.z = c2.x * sg0.z; o0.w = c3.x * sg0.w;
        float4 o1; o1.x = c0.y * sg1.x; o1.y = c1.y * sg1.y; o1.z = c2.y * sg1.z; o1.w = c3.y * sg1.w;
        *(float4*)(gated + row0 * 1024 + h * 64 + dg * 4) = o0;
        *(float4*)(gated + (row0 + 1) * 1024 + h * 64 + dg * 4) = o1;
    }
}

// -------- launcher --------
extern "C" void kernel_launch(void* const* d_in, const int* in_sizes, int n_in,
                              void* d_out, int out_size) {
    const float* query     = (const float*)d_in[0];
    const float* rels      = (const float*)d_in[1];
    const float* attn_mask = (const float*)d_in[2];
    const void*  kpm       = d_in[3];
    const float* proj_w    = (const float*)d_in[4];
    const float* proj_b    = (const float*)d_in[5];
    const float* out_w     = (const float*)d_in[6];
    const float* out_b     = (const float*)d_in[7];
    const float* rels_bias = (const float*)d_in[8];

    float *qkvg_p, *gated_p, *wfb_p, *ofb_p;
    cudaGetSymbolAddress((void**)&qkvg_p,  g_qkvg);
    cudaGetSymbolAddress((void**)&gated_p, g_gated);
    cudaGetSymbolAddress((void**)&wfb_p,   g_w_fb);
    cudaGetSymbolAddress((void**)&ofb_p,   g_out_fb);

    const size_t OUT_E = (size_t)PM * PE;
    const size_t W_E   = (size_t)PB * PL * PL * PH;
    float* out_p;
    float* w_p;
    const size_t osz = (size_t)out_size;
    if (osz >= OUT_E + W_E)      { out_p = (float*)d_out; w_p = (float*)d_out + OUT_E; }
    else if (osz == W_E)         { w_p = (float*)d_out;  out_p = ofb_p; }
    else                         { out_p = (float*)d_out; w_p = wfb_p; }

    static bool attr_set = false;
    const int k3_smem = (8 * 1024 + 32 * 132 + 8 * 17 * 32) * 4;
    if (!attr_set) {
        cudaFuncSetAttribute(attn_av_kernel, cudaFuncAttributeMaxDynamicSharedMemorySize, k3_smem);
        attr_set = true;
    }

    detect_kpm_kernel<<<1, 1>>>((const unsigned char*)kpm);

    sgemm_nt<<<dim3(32, 32), 256>>>(PM, 4096, PE, query, proj_w, proj_b, qkvg_p, 1);

    scores_kernel<<<dim3(32, 32, PB), 256>>>(qkvg_p, rels, attn_mask, kpm, rels_bias, w_p);

    attn_av_kernel<<<dim3(32, PB), 512, k3_smem>>>(qkvg_p, w_p, gated_p);

    sgemm_nt<<<dim3(8, 32), 256>>>(PM, PE, PHID, gated_p, out_w, out_b, out_p, 0);
}